// round 8
// baseline (speedup 1.0000x reference)
#include <cuda_runtime.h>
#include <cuda_fp16.h>
#include <math.h>

#define NN 50000
#define EE 800000
#define INF 128
#define HH 64
#define KK 5
#define EPS 0.001f

// ---------------- scratch (static device globals; no allocations) ----------------
__device__ float  g_h[NN * HH];        // node hidden state (fp32)
__device__ __half g_hs16[NN * HH];     // hs = h@w_s, fp16 (gathered side)
__device__ float  g_hd[NN * HH];       // hd = h@w_d, fp32 (read once per node)
__device__ unsigned short g_q[NN * HH];// final h quantized uint16 (global scale)
__device__ int    g_hmax;              // max(h) as float bits (h >= 0)
__device__ int    g_indeg[NN];
__device__ int    g_off[NN + 1];
__device__ int    g_cursor[NN];
__device__ int    g_ssrc[EE];          // src sorted by dst (CSR payload)

// ---------------- helpers ----------------
__device__ __forceinline__ float sigm(float x) { return 1.0f / (1.0f + expf(-x)); }
__device__ __forceinline__ float softplus(float x) {
    return fmaxf(x, 0.0f) + log1pf(expf(-fabsf(x)));
}
#define MAGIC_C 8388608.0f  // 2^23; as_float(0x4B000000 | q) = 2^23 + q

// expand low/high uint16 of v into float 2^23 + q (one PRMT each)
__device__ __forceinline__ float exlo(unsigned v) {
    return __uint_as_float(__byte_perm(v, 0x4B000000u, 0x7410));
}
__device__ __forceinline__ float exhi(unsigned v) {
    return __uint_as_float(__byte_perm(v, 0x4B000000u, 0x7432));
}

// ---------------- embed: h = node_feat @ emb_w + emb_b ----------------
__global__ void k_embed(const float* __restrict__ x, const float* __restrict__ W,
                        const float* __restrict__ b) {
    __shared__ float sW[INF][HH];   // 32KB
    __shared__ float sx[64][64];    // 16KB (one k-chunk)
    int t = threadIdx.x;
    int tx = t & 15, ty = t >> 4;
    const float4* W4 = (const float4*)W;
    float4* sW4 = (float4*)&sW[0][0];
    for (int i = t; i < INF * HH / 4; i += 256) sW4[i] = W4[i];

    int row0 = blockIdx.x * 64;
    float acc[4][4] = {};

    for (int kc = 0; kc < INF; kc += 64) {
        __syncthreads();
        for (int i = t; i < 1024; i += 256) {
            int r = i >> 4, c = i & 15;
            int row = row0 + r;
            float4 v = make_float4(0.f, 0.f, 0.f, 0.f);
            if (row < NN) v = *(const float4*)&x[row * INF + kc + 4 * c];
            *((float4*)&sx[r][0] + c) = v;
        }
        __syncthreads();
        #pragma unroll 4
        for (int k = 0; k < 64; k++) {
            float4 w = *(const float4*)&sW[kc + k][tx * 4];
            #pragma unroll
            for (int r = 0; r < 4; r++) {
                float xv = sx[ty * 4 + r][k];
                acc[r][0] += xv * w.x; acc[r][1] += xv * w.y;
                acc[r][2] += xv * w.z; acc[r][3] += xv * w.w;
            }
        }
    }
    float4 bb = *(const float4*)&b[tx * 4];
    #pragma unroll
    for (int r = 0; r < 4; r++) {
        int row = row0 + ty * 4 + r;
        if (row < NN) {
            float4 o = make_float4(acc[r][0] + bb.x, acc[r][1] + bb.y,
                                   acc[r][2] + bb.z, acc[r][3] + bb.w);
            *(float4*)&g_h[row * HH + tx * 4] = o;
        }
    }
}

// ---------------- per-layer linear: hs16[n] = h[n]@w_s (fp16), hd[n] = h[n]@w_d ----
__global__ void k_lin(const float* __restrict__ W /* layer slice [128][64] */) {
    __shared__ float sW[HH][2 * HH];  // 32KB: sW[k][j<64]=W_s, [j>=64]=W_d
    __shared__ float sx[64][HH];      // 16KB
    int t = threadIdx.x;
    int tx = t & 31, ty = t >> 5;

    for (int i = t; i < HH * 2 * HH; i += 256) {
        int k = i >> 7, j = i & 127;
        sW[k][j] = (j < HH) ? W[k * HH + j] : W[(HH + k) * HH + (j - HH)];
    }
    int row0 = blockIdx.x * 64;
    for (int i = t; i < 1024; i += 256) {
        int r = i >> 4, c = i & 15;
        int row = row0 + r;
        float4 v = make_float4(0.f, 0.f, 0.f, 0.f);
        if (row < NN) v = *(const float4*)&g_h[row * HH + 4 * c];
        *((float4*)&sx[r][0] + c) = v;
    }
    __syncthreads();

    float acc[8][4] = {};
    #pragma unroll 4
    for (int k = 0; k < HH; k++) {
        float4 w = *(const float4*)&sW[k][tx * 4];
        #pragma unroll
        for (int r = 0; r < 8; r++) {
            float xv = sx[ty * 8 + r][k];
            acc[r][0] += xv * w.x; acc[r][1] += xv * w.y;
            acc[r][2] += xv * w.z; acc[r][3] += xv * w.w;
        }
    }
    #pragma unroll
    for (int r = 0; r < 8; r++) {
        int row = row0 + ty * 8 + r;
        if (row >= NN) continue;
        if (tx < 16) {  // hs columns 0..63 -> fp16
            __half2 p0 = __floats2half2_rn(acc[r][0], acc[r][1]);
            __half2 p1 = __floats2half2_rn(acc[r][2], acc[r][3]);
            uint2 pk = make_uint2(*(unsigned*)&p0, *(unsigned*)&p1);
            *(uint2*)&g_hs16[row * HH + tx * 4] = pk;
        } else {        // hd columns 64..127 -> fp32
            float4 o = make_float4(acc[r][0], acc[r][1], acc[r][2], acc[r][3]);
            *(float4*)&g_hd[row * HH + (tx - 16) * 4] = o;
        }
    }
}

// ---------------- CSR build ----------------
__global__ void k_zero() {
    int i = blockIdx.x * blockDim.x + threadIdx.x;
    if (i < NN) { g_indeg[i] = 0; g_cursor[i] = 0; }
    if (i == 0) g_hmax = 0;
}
__global__ void k_count(const int* __restrict__ dst) {
    int e = blockIdx.x * blockDim.x + threadIdx.x;
    if (e < EE) atomicAdd(&g_indeg[dst[e]], 1);
}
__global__ void k_scan() {  // single block, 1024 threads
    __shared__ int ssum[1024];
    int t = threadIdx.x;
    const int CH = (NN + 1023) / 1024;
    int base = t * CH;
    int s = 0;
    for (int i = 0; i < CH; i++) {
        int idx = base + i;
        if (idx < NN) s += g_indeg[idx];
    }
    ssum[t] = s;
    __syncthreads();
    for (int off = 1; off < 1024; off <<= 1) {
        int v = (t >= off) ? ssum[t - off] : 0;
        __syncthreads();
        ssum[t] += v;
        __syncthreads();
    }
    int run = ssum[t] - s;  // exclusive prefix
    for (int i = 0; i < CH; i++) {
        int idx = base + i;
        if (idx < NN) { g_off[idx] = run; run += g_indeg[idx]; }
    }
    if (t == 1023) g_off[NN] = run;
}
__global__ void k_scatter(const int* __restrict__ src, const int* __restrict__ dst) {
    int e = blockIdx.x * blockDim.x + threadIdx.x;
    if (e < EE) {
        int d = dst[e];
        int p = atomicAdd(&g_cursor[d], 1);
        g_ssrc[g_off[d] + p] = src[e];
    }
}

// ---------------- gather + full node update (one warp per node) ----------------
// Always writes fp32 g_h. last==1 additionally contributes to global max(h).
__global__ void k_gather_update(const float* __restrict__ cb,
                                const float* __restrict__ gamma,
                                const float* __restrict__ beta,
                                const float* __restrict__ mean,
                                const float* __restrict__ var,
                                int last) {
    int warp = (blockIdx.x * blockDim.x + threadIdx.x) >> 5;
    int lane = threadIdx.x & 31;
    if (warp >= NN) return;
    int n = warp;
    int s0 = g_off[n], s1 = g_off[n + 1];
    float a0 = 0.0f, a1 = 0.0f;
    int i = s0;
    for (; i + 3 < s1; i += 4) {
        int sA = g_ssrc[i], sB = g_ssrc[i + 1], sC = g_ssrc[i + 2], sD = g_ssrc[i + 3];
        float2 vA = __half22float2(*(const __half2*)&g_hs16[sA * HH + 2 * lane]);
        float2 vB = __half22float2(*(const __half2*)&g_hs16[sB * HH + 2 * lane]);
        float2 vC = __half22float2(*(const __half2*)&g_hs16[sC * HH + 2 * lane]);
        float2 vD = __half22float2(*(const __half2*)&g_hs16[sD * HH + 2 * lane]);
        a0 += (vA.x + vB.x) + (vC.x + vD.x);
        a1 += (vA.y + vB.y) + (vC.y + vD.y);
    }
    for (; i < s1; i++) {
        int s = g_ssrc[i];
        float2 v = __half22float2(*(const __half2*)&g_hs16[s * HH + 2 * lane]);
        a0 += v.x; a1 += v.y;
    }
    float deg = (float)(s1 - s0);
    float2 hd = *(const float2*)&g_hd[n * HH + 2 * lane];
    int j0 = 2 * lane, j1 = 2 * lane + 1;
    float agg0 = a0 + deg * (hd.x + cb[j0]);
    float agg1 = a1 + deg * (hd.y + cb[j1]);
    float2 hold = *(const float2*)&g_h[n * HH + 2 * lane];
    float x0 = sigm(agg0) + softplus(hold.x);
    float x1 = sigm(agg1) + softplus(hold.y);
    x0 = gamma[j0] * (x0 - mean[j0]) * rsqrtf(var[j0] + EPS) + beta[j0];
    x1 = gamma[j1] * (x1 - mean[j1]) * rsqrtf(var[j1] + EPS) + beta[j1];
    x0 = fmaxf(x0, 0.0f);
    x1 = fmaxf(x1, 0.0f);
    *(float2*)&g_h[n * HH + 2 * lane] = make_float2(x0, x1);
    if (last) {
        float m = fmaxf(x0, x1);
        m = fmaxf(m, __shfl_xor_sync(0xffffffffu, m, 16));
        m = fmaxf(m, __shfl_xor_sync(0xffffffffu, m, 8));
        m = fmaxf(m, __shfl_xor_sync(0xffffffffu, m, 4));
        m = fmaxf(m, __shfl_xor_sync(0xffffffffu, m, 2));
        m = fmaxf(m, __shfl_xor_sync(0xffffffffu, m, 1));
        if (lane == 0) atomicMax(&g_hmax, __float_as_int(m));  // h >= 0
    }
}

// ---------------- quantize final h -> uint16 with global scale ----------------
__global__ void k_quant() {
    int i = blockIdx.x * blockDim.x + threadIdx.x;  // one per 4 elements
    if (i >= NN * HH / 4) return;
    float hmax = fmaxf(__int_as_float(g_hmax), 1e-20f);
    float inv = 65535.0f / hmax;
    float4 v = *(const float4*)&g_h[4 * i];
    unsigned q0 = __float2uint_rn(fminf(v.x * inv, 65535.0f));
    unsigned q1 = __float2uint_rn(fminf(v.y * inv, 65535.0f));
    unsigned q2 = __float2uint_rn(fminf(v.z * inv, 65535.0f));
    unsigned q3 = __float2uint_rn(fminf(v.w * inv, 65535.0f));
    uint2 pk = make_uint2(q0 | (q1 << 16), q2 | (q3 << 16));
    *(uint2*)&g_q[4 * i] = pk;
}

// ---------------- fused scoring: pos + K negs per edge, 8 threads/edge ----------
// score = sum_j h[s][j] * h[d][j] * w[j], with h = (E(q) - C) * s_q, s_q = hmax/65535.
// Fold: aw[j] = (E(q_s[j]) - C) * w[j] * s_q^2; score = sum aw[j]*E(q_d[j]) - C*sum(aw).
__global__ void k_score(const int* __restrict__ src, const int* __restrict__ dst,
                        const int* __restrict__ neg_dst, const float* __restrict__ wrel,
                        float* __restrict__ out) {
    int gid = blockIdx.x * blockDim.x + threadIdx.x;
    int e = gid >> 3;
    int c = gid & 7;
    if (e >= EE) return;
    float sq = fmaxf(__int_as_float(g_hmax), 1e-20f) * (1.0f / 65535.0f);
    float ss = sq * sq;
    float wss[8];
    #pragma unroll
    for (int j = 0; j < 8; j++) wss[j] = wrel[8 * c + j] * ss;

    int s = src[e];
    int d = dst[e];
    int nd[KK];
    #pragma unroll
    for (int k = 0; k < KK; k++) nd[k] = neg_dst[e * KK + k];

    uint4 qs = *(const uint4*)&g_q[s * HH + 8 * c];
    uint4 qp = *(const uint4*)&g_q[d * HH + 8 * c];
    uint4 qn[KK];
    #pragma unroll
    for (int k = 0; k < KK; k++)
        qn[k] = *(const uint4*)&g_q[nd[k] * HH + 8 * c];

    // src-side coefficients
    float aw[8];
    const unsigned* vs = (const unsigned*)&qs;
    #pragma unroll
    for (int i = 0; i < 4; i++) {
        aw[2 * i]     = (exlo(vs[i]) - MAGIC_C) * wss[2 * i];
        aw[2 * i + 1] = (exhi(vs[i]) - MAGIC_C) * wss[2 * i + 1];
    }
    float awsum = 0.0f;
    #pragma unroll
    for (int j = 0; j < 8; j++) awsum += aw[j];

    // positive
    {
        const unsigned* vd = (const unsigned*)&qp;
        float p = 0.0f;
        #pragma unroll
        for (int i = 0; i < 4; i++) {
            p = fmaf(aw[2 * i],     exlo(vd[i]), p);
            p = fmaf(aw[2 * i + 1], exhi(vd[i]), p);
        }
        p = fmaf(-MAGIC_C, awsum, p);
        p += __shfl_xor_sync(0xffffffffu, p, 4);
        p += __shfl_xor_sync(0xffffffffu, p, 2);
        p += __shfl_xor_sync(0xffffffffu, p, 1);
        if (c == 0) out[e] = p;
    }
    // negatives
    #pragma unroll
    for (int k = 0; k < KK; k++) {
        const unsigned* vd = (const unsigned*)&qn[k];
        float p = 0.0f;
        #pragma unroll
        for (int i = 0; i < 4; i++) {
            p = fmaf(aw[2 * i],     exlo(vd[i]), p);
            p = fmaf(aw[2 * i + 1], exhi(vd[i]), p);
        }
        p = fmaf(-MAGIC_C, awsum, p);
        p += __shfl_xor_sync(0xffffffffu, p, 4);
        p += __shfl_xor_sync(0xffffffffu, p, 2);
        p += __shfl_xor_sync(0xffffffffu, p, 1);
        if (c == 0) out[EE + e * KK + k] = p;
    }
}

// ---------------- launch ----------------
extern "C" void kernel_launch(void* const* d_in, const int* in_sizes, int n_in,
                              void* d_out, int out_size) {
    const float* node_feat = (const float*)d_in[0];
    const float* emb_w     = (const float*)d_in[1];
    const float* emb_b     = (const float*)d_in[2];
    const float* conv_w    = (const float*)d_in[3];
    const float* conv_b    = (const float*)d_in[4];
    const float* bn_gamma  = (const float*)d_in[5];
    const float* bn_beta   = (const float*)d_in[6];
    const float* bn_mean   = (const float*)d_in[7];
    const float* bn_var    = (const float*)d_in[8];
    const float* w_rel     = (const float*)d_in[9];
    const int*   src       = (const int*)d_in[10];
    const int*   dst       = (const int*)d_in[11];
    const int*   neg_dst   = (const int*)d_in[12];
    float* out = (float*)d_out;

    // CSR build (+ hmax reset)
    k_zero<<<(NN + 255) / 256, 256>>>();
    k_count<<<(EE + 255) / 256, 256>>>(dst);
    k_scan<<<1, 1024>>>();
    k_scatter<<<(EE + 255) / 256, 256>>>(src, dst);

    // embedding
    k_embed<<<(NN + 63) / 64, 256>>>(node_feat, emb_w, emb_b);

    // two conv layers
    for (int i = 0; i < 2; i++) {
        k_lin<<<(NN + 63) / 64, 256>>>(conv_w + (size_t)i * 2 * HH * HH);
        k_gather_update<<<(NN * 32 + 255) / 256, 256>>>(
            conv_b + i * HH, bn_gamma + i * HH, bn_beta + i * HH,
            bn_mean + i * HH, bn_var + i * HH, (i == 1) ? 1 : 0);
    }

    // quantize final h, then fused scoring
    k_quant<<<(NN * HH / 4 + 255) / 256, 256>>>();
    k_score<<<(EE * 8 + 255) / 256, 256>>>(src, dst, neg_dst, w_rel, out);
}

// round 9
// speedup vs baseline: 1.0035x; 1.0035x over previous
#include <cuda_runtime.h>
#include <cuda_fp16.h>
#include <math.h>

#define NN 50000
#define EE 800000
#define INF 128
#define HH 64
#define KK 5
#define EPS 0.001f

// ---------------- scratch (static device globals; no allocations) ----------------
__device__ float  g_h[NN * HH];        // node hidden state (fp32)
__device__ __half g_hs16[NN * HH];     // hs = h@w_s, fp16 (gathered side)
__device__ float  g_hd[NN * HH];       // hd = h@w_d, fp32 (read once per node)
__device__ unsigned short g_q[NN * HH];  // final h quantized uint16 (scale hmax)
__device__ unsigned short g_qw[NN * HH]; // final h*w, biased uint16 (scale hwmax)
__device__ int    g_hmax;              // max(h) as float bits (h >= 0)
__device__ int    g_hwmax;             // max(|h*w|) as float bits
__device__ int    g_indeg[NN];
__device__ int    g_off[NN + 1];
__device__ int    g_cursor[NN];
__device__ int    g_ssrc[EE];          // src sorted by dst (CSR payload)

// ---------------- helpers ----------------
__device__ __forceinline__ float sigm(float x) { return 1.0f / (1.0f + expf(-x)); }
__device__ __forceinline__ float softplus(float x) {
    return fmaxf(x, 0.0f) + log1pf(expf(-fabsf(x)));
}
#define MAGIC_C  8388608.0f   // 2^23
#define MAGIC_C2 8421376.0f   // 2^23 + 32768 (biased)

// expand low/high uint16 of v into float 2^23 + q (one PRMT each)
__device__ __forceinline__ float exlo(unsigned v) {
    return __uint_as_float(__byte_perm(v, 0x4B000000u, 0x7410));
}
__device__ __forceinline__ float exhi(unsigned v) {
    return __uint_as_float(__byte_perm(v, 0x4B000000u, 0x7432));
}

// ---------------- embed: h = node_feat @ emb_w + emb_b ----------------
__global__ void k_embed(const float* __restrict__ x, const float* __restrict__ W,
                        const float* __restrict__ b) {
    __shared__ float sW[INF][HH];   // 32KB
    __shared__ float sx[64][64];    // 16KB (one k-chunk)
    int t = threadIdx.x;
    int tx = t & 15, ty = t >> 4;
    const float4* W4 = (const float4*)W;
    float4* sW4 = (float4*)&sW[0][0];
    for (int i = t; i < INF * HH / 4; i += 256) sW4[i] = W4[i];

    int row0 = blockIdx.x * 64;
    float acc[4][4] = {};

    for (int kc = 0; kc < INF; kc += 64) {
        __syncthreads();
        for (int i = t; i < 1024; i += 256) {
            int r = i >> 4, c = i & 15;
            int row = row0 + r;
            float4 v = make_float4(0.f, 0.f, 0.f, 0.f);
            if (row < NN) v = *(const float4*)&x[row * INF + kc + 4 * c];
            *((float4*)&sx[r][0] + c) = v;
        }
        __syncthreads();
        #pragma unroll 4
        for (int k = 0; k < 64; k++) {
            float4 w = *(const float4*)&sW[kc + k][tx * 4];
            #pragma unroll
            for (int r = 0; r < 4; r++) {
                float xv = sx[ty * 4 + r][k];
                acc[r][0] += xv * w.x; acc[r][1] += xv * w.y;
                acc[r][2] += xv * w.z; acc[r][3] += xv * w.w;
            }
        }
    }
    float4 bb = *(const float4*)&b[tx * 4];
    #pragma unroll
    for (int r = 0; r < 4; r++) {
        int row = row0 + ty * 4 + r;
        if (row < NN) {
            float4 o = make_float4(acc[r][0] + bb.x, acc[r][1] + bb.y,
                                   acc[r][2] + bb.z, acc[r][3] + bb.w);
            *(float4*)&g_h[row * HH + tx * 4] = o;
        }
    }
}

// ---------------- per-layer linear: hs16[n] = h[n]@w_s (fp16), hd[n] = h[n]@w_d ----
__global__ void k_lin(const float* __restrict__ W /* layer slice [128][64] */) {
    __shared__ float sW[HH][2 * HH];  // 32KB: sW[k][j<64]=W_s, [j>=64]=W_d
    __shared__ float sx[64][HH];      // 16KB
    int t = threadIdx.x;
    int tx = t & 31, ty = t >> 5;

    for (int i = t; i < HH * 2 * HH; i += 256) {
        int k = i >> 7, j = i & 127;
        sW[k][j] = (j < HH) ? W[k * HH + j] : W[(HH + k) * HH + (j - HH)];
    }
    int row0 = blockIdx.x * 64;
    for (int i = t; i < 1024; i += 256) {
        int r = i >> 4, c = i & 15;
        int row = row0 + r;
        float4 v = make_float4(0.f, 0.f, 0.f, 0.f);
        if (row < NN) v = *(const float4*)&g_h[row * HH + 4 * c];
        *((float4*)&sx[r][0] + c) = v;
    }
    __syncthreads();

    float acc[8][4] = {};
    #pragma unroll 4
    for (int k = 0; k < HH; k++) {
        float4 w = *(const float4*)&sW[k][tx * 4];
        #pragma unroll
        for (int r = 0; r < 8; r++) {
            float xv = sx[ty * 8 + r][k];
            acc[r][0] += xv * w.x; acc[r][1] += xv * w.y;
            acc[r][2] += xv * w.z; acc[r][3] += xv * w.w;
        }
    }
    #pragma unroll
    for (int r = 0; r < 8; r++) {
        int row = row0 + ty * 8 + r;
        if (row >= NN) continue;
        if (tx < 16) {  // hs columns 0..63 -> fp16
            __half2 p0 = __floats2half2_rn(acc[r][0], acc[r][1]);
            __half2 p1 = __floats2half2_rn(acc[r][2], acc[r][3]);
            uint2 pk = make_uint2(*(unsigned*)&p0, *(unsigned*)&p1);
            *(uint2*)&g_hs16[row * HH + tx * 4] = pk;
        } else {        // hd columns 64..127 -> fp32
            float4 o = make_float4(acc[r][0], acc[r][1], acc[r][2], acc[r][3]);
            *(float4*)&g_hd[row * HH + (tx - 16) * 4] = o;
        }
    }
}

// ---------------- CSR build ----------------
__global__ void k_zero() {
    int i = blockIdx.x * blockDim.x + threadIdx.x;
    if (i < NN) { g_indeg[i] = 0; g_cursor[i] = 0; }
    if (i == 0) { g_hmax = 0; g_hwmax = 0; }
}
__global__ void k_count(const int* __restrict__ dst) {
    int i = blockIdx.x * blockDim.x + threadIdx.x;
    if (i < EE / 4) {
        int4 d = ((const int4*)dst)[i];
        atomicAdd(&g_indeg[d.x], 1);
        atomicAdd(&g_indeg[d.y], 1);
        atomicAdd(&g_indeg[d.z], 1);
        atomicAdd(&g_indeg[d.w], 1);
    }
}
__global__ void k_scan() {  // single block, 1024 threads
    __shared__ int ssum[1024];
    int t = threadIdx.x;
    const int CH = (NN + 1023) / 1024;
    int base = t * CH;
    int s = 0;
    for (int i = 0; i < CH; i++) {
        int idx = base + i;
        if (idx < NN) s += g_indeg[idx];
    }
    ssum[t] = s;
    __syncthreads();
    for (int off = 1; off < 1024; off <<= 1) {
        int v = (t >= off) ? ssum[t - off] : 0;
        __syncthreads();
        ssum[t] += v;
        __syncthreads();
    }
    int run = ssum[t] - s;  // exclusive prefix
    for (int i = 0; i < CH; i++) {
        int idx = base + i;
        if (idx < NN) { g_off[idx] = run; run += g_indeg[idx]; }
    }
    if (t == 1023) g_off[NN] = run;
}
__global__ void k_scatter(const int* __restrict__ src, const int* __restrict__ dst) {
    int i = blockIdx.x * blockDim.x + threadIdx.x;
    if (i < EE / 4) {
        int4 d = ((const int4*)dst)[i];
        int4 s = ((const int4*)src)[i];
        int p;
        p = atomicAdd(&g_cursor[d.x], 1); g_ssrc[g_off[d.x] + p] = s.x;
        p = atomicAdd(&g_cursor[d.y], 1); g_ssrc[g_off[d.y] + p] = s.y;
        p = atomicAdd(&g_cursor[d.z], 1); g_ssrc[g_off[d.z] + p] = s.z;
        p = atomicAdd(&g_cursor[d.w], 1); g_ssrc[g_off[d.w] + p] = s.w;
    }
}

// ---------------- gather + full node update (one warp per node) ----------------
// Always writes fp32 g_h. last==1 additionally tracks max(h) and max|h*w|.
__global__ void k_gather_update(const float* __restrict__ cb,
                                const float* __restrict__ gamma,
                                const float* __restrict__ beta,
                                const float* __restrict__ mean,
                                const float* __restrict__ var,
                                const float* __restrict__ wrel,
                                int last) {
    int warp = (blockIdx.x * blockDim.x + threadIdx.x) >> 5;
    int lane = threadIdx.x & 31;
    if (warp >= NN) return;
    int n = warp;
    int s0 = g_off[n], s1 = g_off[n + 1];
    float a0 = 0.0f, a1 = 0.0f;
    int i = s0;
    for (; i + 3 < s1; i += 4) {
        int sA = g_ssrc[i], sB = g_ssrc[i + 1], sC = g_ssrc[i + 2], sD = g_ssrc[i + 3];
        float2 vA = __half22float2(*(const __half2*)&g_hs16[sA * HH + 2 * lane]);
        float2 vB = __half22float2(*(const __half2*)&g_hs16[sB * HH + 2 * lane]);
        float2 vC = __half22float2(*(const __half2*)&g_hs16[sC * HH + 2 * lane]);
        float2 vD = __half22float2(*(const __half2*)&g_hs16[sD * HH + 2 * lane]);
        a0 += (vA.x + vB.x) + (vC.x + vD.x);
        a1 += (vA.y + vB.y) + (vC.y + vD.y);
    }
    for (; i < s1; i++) {
        int s = g_ssrc[i];
        float2 v = __half22float2(*(const __half2*)&g_hs16[s * HH + 2 * lane]);
        a0 += v.x; a1 += v.y;
    }
    float deg = (float)(s1 - s0);
    float2 hd = *(const float2*)&g_hd[n * HH + 2 * lane];
    int j0 = 2 * lane, j1 = 2 * lane + 1;
    float agg0 = a0 + deg * (hd.x + cb[j0]);
    float agg1 = a1 + deg * (hd.y + cb[j1]);
    float2 hold = *(const float2*)&g_h[n * HH + 2 * lane];
    float x0 = sigm(agg0) + softplus(hold.x);
    float x1 = sigm(agg1) + softplus(hold.y);
    x0 = gamma[j0] * (x0 - mean[j0]) * rsqrtf(var[j0] + EPS) + beta[j0];
    x1 = gamma[j1] * (x1 - mean[j1]) * rsqrtf(var[j1] + EPS) + beta[j1];
    x0 = fmaxf(x0, 0.0f);
    x1 = fmaxf(x1, 0.0f);
    *(float2*)&g_h[n * HH + 2 * lane] = make_float2(x0, x1);
    if (last) {
        float m = fmaxf(x0, x1);
        float mw = fmaxf(fabsf(x0 * wrel[j0]), fabsf(x1 * wrel[j1]));
        m = fmaxf(m, __shfl_xor_sync(0xffffffffu, m, 16));
        m = fmaxf(m, __shfl_xor_sync(0xffffffffu, m, 8));
        m = fmaxf(m, __shfl_xor_sync(0xffffffffu, m, 4));
        m = fmaxf(m, __shfl_xor_sync(0xffffffffu, m, 2));
        m = fmaxf(m, __shfl_xor_sync(0xffffffffu, m, 1));
        mw = fmaxf(mw, __shfl_xor_sync(0xffffffffu, mw, 16));
        mw = fmaxf(mw, __shfl_xor_sync(0xffffffffu, mw, 8));
        mw = fmaxf(mw, __shfl_xor_sync(0xffffffffu, mw, 4));
        mw = fmaxf(mw, __shfl_xor_sync(0xffffffffu, mw, 2));
        mw = fmaxf(mw, __shfl_xor_sync(0xffffffffu, mw, 1));
        if (lane == 0) {
            atomicMax(&g_hmax, __float_as_int(m));    // h >= 0
            atomicMax(&g_hwmax, __float_as_int(mw));  // |hw| >= 0
        }
    }
}

// ---------------- quantize final h -> uint16, h*w -> biased uint16 ----------------
__global__ void k_quant(const float* __restrict__ wrel) {
    int i = blockIdx.x * blockDim.x + threadIdx.x;  // one per 4 elements
    if (i >= NN * HH / 4) return;
    float hmax = fmaxf(__int_as_float(g_hmax), 1e-20f);
    float hwmax = fmaxf(__int_as_float(g_hwmax), 1e-20f);
    float inv = 65535.0f / hmax;
    float invw = 32767.0f / hwmax;
    int jc = (4 * i) & 63;
    float4 w = *(const float4*)&wrel[jc];
    float4 v = *(const float4*)&g_h[4 * i];
    unsigned q0 = __float2uint_rn(fminf(v.x * inv, 65535.0f));
    unsigned q1 = __float2uint_rn(fminf(v.y * inv, 65535.0f));
    unsigned q2 = __float2uint_rn(fminf(v.z * inv, 65535.0f));
    unsigned q3 = __float2uint_rn(fminf(v.w * inv, 65535.0f));
    *(uint2*)&g_q[4 * i] = make_uint2(q0 | (q1 << 16), q2 | (q3 << 16));
    int w0 = __float2int_rn(v.x * w.x * invw) + 32768;
    int w1 = __float2int_rn(v.y * w.y * invw) + 32768;
    int w2 = __float2int_rn(v.z * w.z * invw) + 32768;
    int w3 = __float2int_rn(v.w * w.w * invw) + 32768;
    *(uint2*)&g_qw[4 * i] = make_uint2((unsigned)w0 | ((unsigned)w1 << 16),
                                       (unsigned)w2 | ((unsigned)w3 << 16));
}

// ---------------- fused scoring: pos + K negs per edge, 8 threads/edge ----------
// hw_s[j] = (E(qw)-C2)*s2,  h_d[j] = (E(q)-C)*s1
// aw[j] = (E(qw)-C2)*(s1*s2);  score = sum aw[j]*E(q_d[j]) - C*sum(aw)
__global__ void k_score(const int* __restrict__ src, const int* __restrict__ dst,
                        const int* __restrict__ neg_dst, float* __restrict__ out) {
    int gid = blockIdx.x * blockDim.x + threadIdx.x;
    int e = gid >> 3;
    int c = gid & 7;
    if (e >= EE) return;
    float s1 = __int_as_float(g_hmax) * (1.0f / 65535.0f);
    float s2 = __int_as_float(g_hwmax) * (1.0f / 32767.0f);
    float ss = s1 * s2;
    float c2ss = MAGIC_C2 * ss;

    int s = src[e];
    int d = dst[e];
    int nd[KK];
    #pragma unroll
    for (int k = 0; k < KK; k++) nd[k] = neg_dst[e * KK + k];

    uint4 qs = *(const uint4*)&g_qw[s * HH + 8 * c];
    uint4 qp = *(const uint4*)&g_q[d * HH + 8 * c];
    uint4 qn[KK];
    #pragma unroll
    for (int k = 0; k < KK; k++)
        qn[k] = *(const uint4*)&g_q[nd[k] * HH + 8 * c];

    float aw[8];
    const unsigned* vs = (const unsigned*)&qs;
    #pragma unroll
    for (int i = 0; i < 4; i++) {
        aw[2 * i]     = fmaf(exlo(vs[i]), ss, -c2ss);
        aw[2 * i + 1] = fmaf(exhi(vs[i]), ss, -c2ss);
    }
    float awsum = 0.0f;
    #pragma unroll
    for (int j = 0; j < 8; j++) awsum += aw[j];
    float base = -MAGIC_C * awsum;

    {
        const unsigned* vd = (const unsigned*)&qp;
        float p = base;
        #pragma unroll
        for (int i = 0; i < 4; i++) {
            p = fmaf(aw[2 * i],     exlo(vd[i]), p);
            p = fmaf(aw[2 * i + 1], exhi(vd[i]), p);
        }
        p += __shfl_xor_sync(0xffffffffu, p, 4);
        p += __shfl_xor_sync(0xffffffffu, p, 2);
        p += __shfl_xor_sync(0xffffffffu, p, 1);
        if (c == 0) out[e] = p;
    }
    #pragma unroll
    for (int k = 0; k < KK; k++) {
        const unsigned* vd = (const unsigned*)&qn[k];
        float p = base;
        #pragma unroll
        for (int i = 0; i < 4; i++) {
            p = fmaf(aw[2 * i],     exlo(vd[i]), p);
            p = fmaf(aw[2 * i + 1], exhi(vd[i]), p);
        }
        p += __shfl_xor_sync(0xffffffffu, p, 4);
        p += __shfl_xor_sync(0xffffffffu, p, 2);
        p += __shfl_xor_sync(0xffffffffu, p, 1);
        if (c == 0) out[EE + e * KK + k] = p;
    }
}

// ---------------- launch ----------------
extern "C" void kernel_launch(void* const* d_in, const int* in_sizes, int n_in,
                              void* d_out, int out_size) {
    const float* node_feat = (const float*)d_in[0];
    const float* emb_w     = (const float*)d_in[1];
    const float* emb_b     = (const float*)d_in[2];
    const float* conv_w    = (const float*)d_in[3];
    const float* conv_b    = (const float*)d_in[4];
    const float* bn_gamma  = (const float*)d_in[5];
    const float* bn_beta   = (const float*)d_in[6];
    const float* bn_mean   = (const float*)d_in[7];
    const float* bn_var    = (const float*)d_in[8];
    const float* w_rel     = (const float*)d_in[9];
    const int*   src       = (const int*)d_in[10];
    const int*   dst       = (const int*)d_in[11];
    const int*   neg_dst   = (const int*)d_in[12];
    float* out = (float*)d_out;

    // side stream + fork/join events, created once (before any capture)
    static cudaStream_t s1 = nullptr;
    static cudaEvent_t eF = nullptr, eJ = nullptr;
    if (!s1) {
        cudaStreamCreateWithFlags(&s1, cudaStreamNonBlocking);
        cudaEventCreateWithFlags(&eF, cudaEventDisableTiming);
        cudaEventCreateWithFlags(&eJ, cudaEventDisableTiming);
    }

    // fork: CSR build on s1, concurrent with embed + lin0 on default stream
    cudaEventRecord(eF, 0);
    cudaStreamWaitEvent(s1, eF, 0);
    k_zero<<<(NN + 255) / 256, 256, 0, s1>>>();
    k_count<<<(EE / 4 + 255) / 256, 256, 0, s1>>>(dst);
    k_scan<<<1, 1024, 0, s1>>>();
    k_scatter<<<(EE / 4 + 255) / 256, 256, 0, s1>>>(src, dst);
    cudaEventRecord(eJ, s1);

    // embedding + first linear on default stream (independent of CSR)
    k_embed<<<(NN + 63) / 64, 256>>>(node_feat, emb_w, emb_b);
    k_lin<<<(NN + 63) / 64, 256>>>(conv_w);

    // join: gather needs CSR
    cudaStreamWaitEvent(0, eJ, 0);

    k_gather_update<<<(NN * 32 + 255) / 256, 256>>>(
        conv_b, bn_gamma, bn_beta, bn_mean, bn_var, w_rel, 0);

    k_lin<<<(NN + 63) / 64, 256>>>(conv_w + (size_t)2 * HH * HH);
    k_gather_update<<<(NN * 32 + 255) / 256, 256>>>(
        conv_b + HH, bn_gamma + HH, bn_beta + HH, bn_mean + HH, bn_var + HH,
        w_rel, 1);

    // quantize final h (and h*w), then fused scoring
    k_quant<<<(NN * HH / 4 + 255) / 256, 256>>>(w_rel);
    k_score<<<(EE * 8 + 255) / 256, 256>>>(src, dst, neg_dst, out);
}

// round 10
// speedup vs baseline: 1.0576x; 1.0539x over previous
#include <cuda_runtime.h>
#include <cuda_fp16.h>
#include <math.h>

#define NN 50000
#define EE 800000
#define INF 128
#define HH 64
#define KK 5
#define EPS 0.001f

// ---------------- scratch (static device globals; no allocations) ----------------
__device__ float  g_h[NN * HH];        // node hidden state (fp32, inter-layer)
__device__ __half g_hs16[NN * HH];     // hs = h@w_s, fp16 (gathered side)
__device__ float  g_hd[NN * HH];       // hd = h@w_d, fp32 (read once per node)
__device__ unsigned short g_q[NN * HH];  // final h, uint16, per-node scale sB
__device__ unsigned short g_qw[NN * HH]; // final h*w, biased uint16, per-node scale sA
__device__ float  g_sA[NN];            // src-side scale: rowmax|h*w| / 32767
__device__ float  g_sB[NN];            // dst-side scale: rowmax(h) / 65535
__device__ int    g_indeg[NN];
__device__ int    g_off[NN + 1];
__device__ int    g_cursor[NN];
__device__ int    g_ssrc[EE];          // src sorted by dst (CSR payload)

// ---------------- helpers ----------------
__device__ __forceinline__ float sigm(float x) { return 1.0f / (1.0f + expf(-x)); }
__device__ __forceinline__ float softplus(float x) {
    return fmaxf(x, 0.0f) + log1pf(expf(-fabsf(x)));
}
#define MAGIC_C  8388608.0f   // 2^23
#define MAGIC_C2 8421376.0f   // 2^23 + 32768 (biased)

// expand low/high uint16 of v into float 2^23 + q (one PRMT each)
__device__ __forceinline__ float exlo(unsigned v) {
    return __uint_as_float(__byte_perm(v, 0x4B000000u, 0x7410));
}
__device__ __forceinline__ float exhi(unsigned v) {
    return __uint_as_float(__byte_perm(v, 0x4B000000u, 0x7432));
}

// ---------------- embed: h = node_feat @ emb_w + emb_b ----------------
__global__ void k_embed(const float* __restrict__ x, const float* __restrict__ W,
                        const float* __restrict__ b) {
    __shared__ float sW[INF][HH];   // 32KB
    __shared__ float sx[64][64];    // 16KB (one k-chunk)
    int t = threadIdx.x;
    int tx = t & 15, ty = t >> 4;
    const float4* W4 = (const float4*)W;
    float4* sW4 = (float4*)&sW[0][0];
    for (int i = t; i < INF * HH / 4; i += 256) sW4[i] = W4[i];

    int row0 = blockIdx.x * 64;
    float acc[4][4] = {};

    for (int kc = 0; kc < INF; kc += 64) {
        __syncthreads();
        for (int i = t; i < 1024; i += 256) {
            int r = i >> 4, c = i & 15;
            int row = row0 + r;
            float4 v = make_float4(0.f, 0.f, 0.f, 0.f);
            if (row < NN) v = *(const float4*)&x[row * INF + kc + 4 * c];
            *((float4*)&sx[r][0] + c) = v;
        }
        __syncthreads();
        #pragma unroll 4
        for (int k = 0; k < 64; k++) {
            float4 w = *(const float4*)&sW[kc + k][tx * 4];
            #pragma unroll
            for (int r = 0; r < 4; r++) {
                float xv = sx[ty * 4 + r][k];
                acc[r][0] += xv * w.x; acc[r][1] += xv * w.y;
                acc[r][2] += xv * w.z; acc[r][3] += xv * w.w;
            }
        }
    }
    float4 bb = *(const float4*)&b[tx * 4];
    #pragma unroll
    for (int r = 0; r < 4; r++) {
        int row = row0 + ty * 4 + r;
        if (row < NN) {
            float4 o = make_float4(acc[r][0] + bb.x, acc[r][1] + bb.y,
                                   acc[r][2] + bb.z, acc[r][3] + bb.w);
            *(float4*)&g_h[row * HH + tx * 4] = o;
        }
    }
}

// ---------------- per-layer linear: hs16[n] = h[n]@w_s (fp16), hd[n] = h[n]@w_d ----
__global__ void k_lin(const float* __restrict__ W /* layer slice [128][64] */) {
    __shared__ float sW[HH][2 * HH];  // 32KB: sW[k][j<64]=W_s, [j>=64]=W_d
    __shared__ float sx[64][HH];      // 16KB
    int t = threadIdx.x;
    int tx = t & 31, ty = t >> 5;

    for (int i = t; i < HH * 2 * HH; i += 256) {
        int k = i >> 7, j = i & 127;
        sW[k][j] = (j < HH) ? W[k * HH + j] : W[(HH + k) * HH + (j - HH)];
    }
    int row0 = blockIdx.x * 64;
    for (int i = t; i < 1024; i += 256) {
        int r = i >> 4, c = i & 15;
        int row = row0 + r;
        float4 v = make_float4(0.f, 0.f, 0.f, 0.f);
        if (row < NN) v = *(const float4*)&g_h[row * HH + 4 * c];
        *((float4*)&sx[r][0] + c) = v;
    }
    __syncthreads();

    float acc[8][4] = {};
    #pragma unroll 4
    for (int k = 0; k < HH; k++) {
        float4 w = *(const float4*)&sW[k][tx * 4];
        #pragma unroll
        for (int r = 0; r < 8; r++) {
            float xv = sx[ty * 8 + r][k];
            acc[r][0] += xv * w.x; acc[r][1] += xv * w.y;
            acc[r][2] += xv * w.z; acc[r][3] += xv * w.w;
        }
    }
    #pragma unroll
    for (int r = 0; r < 8; r++) {
        int row = row0 + ty * 8 + r;
        if (row >= NN) continue;
        if (tx < 16) {  // hs columns 0..63 -> fp16
            __half2 p0 = __floats2half2_rn(acc[r][0], acc[r][1]);
            __half2 p1 = __floats2half2_rn(acc[r][2], acc[r][3]);
            uint2 pk = make_uint2(*(unsigned*)&p0, *(unsigned*)&p1);
            *(uint2*)&g_hs16[row * HH + tx * 4] = pk;
        } else {        // hd columns 64..127 -> fp32
            float4 o = make_float4(acc[r][0], acc[r][1], acc[r][2], acc[r][3]);
            *(float4*)&g_hd[row * HH + (tx - 16) * 4] = o;
        }
    }
}

// ---------------- CSR build ----------------
__global__ void k_zero() {
    int i = blockIdx.x * blockDim.x + threadIdx.x;
    if (i < NN) { g_indeg[i] = 0; g_cursor[i] = 0; }
}
__global__ void k_count(const int* __restrict__ dst) {
    int e = blockIdx.x * blockDim.x + threadIdx.x;
    if (e < EE) atomicAdd(&g_indeg[dst[e]], 1);
}
__global__ void k_scan() {  // single block, 1024 threads
    __shared__ int ssum[1024];
    int t = threadIdx.x;
    const int CH = (NN + 1023) / 1024;
    int base = t * CH;
    int s = 0;
    for (int i = 0; i < CH; i++) {
        int idx = base + i;
        if (idx < NN) s += g_indeg[idx];
    }
    ssum[t] = s;
    __syncthreads();
    for (int off = 1; off < 1024; off <<= 1) {
        int v = (t >= off) ? ssum[t - off] : 0;
        __syncthreads();
        ssum[t] += v;
        __syncthreads();
    }
    int run = ssum[t] - s;  // exclusive prefix
    for (int i = 0; i < CH; i++) {
        int idx = base + i;
        if (idx < NN) { g_off[idx] = run; run += g_indeg[idx]; }
    }
    if (t == 1023) g_off[NN] = run;
}
__global__ void k_scatter(const int* __restrict__ src, const int* __restrict__ dst) {
    int e = blockIdx.x * blockDim.x + threadIdx.x;
    if (e < EE) {
        int d = dst[e];
        int p = atomicAdd(&g_cursor[d], 1);
        g_ssrc[g_off[d] + p] = src[e];
    }
}

// ---------------- gather + full node update (one warp per node) ----------------
// last==0: writes fp32 g_h.
// last==1: quantizes in-register (per-node scales) -> g_q, g_qw, g_sA, g_sB.
__global__ void k_gather_update(const float* __restrict__ cb,
                                const float* __restrict__ gamma,
                                const float* __restrict__ beta,
                                const float* __restrict__ mean,
                                const float* __restrict__ var,
                                const float* __restrict__ wrel,
                                int last) {
    int warp = (blockIdx.x * blockDim.x + threadIdx.x) >> 5;
    int lane = threadIdx.x & 31;
    if (warp >= NN) return;
    int n = warp;
    int s0 = g_off[n], s1 = g_off[n + 1];
    float a0 = 0.0f, a1 = 0.0f;
    int i = s0;
    for (; i + 3 < s1; i += 4) {
        int sA = g_ssrc[i], sB = g_ssrc[i + 1], sC = g_ssrc[i + 2], sD = g_ssrc[i + 3];
        float2 vA = __half22float2(*(const __half2*)&g_hs16[sA * HH + 2 * lane]);
        float2 vB = __half22float2(*(const __half2*)&g_hs16[sB * HH + 2 * lane]);
        float2 vC = __half22float2(*(const __half2*)&g_hs16[sC * HH + 2 * lane]);
        float2 vD = __half22float2(*(const __half2*)&g_hs16[sD * HH + 2 * lane]);
        a0 += (vA.x + vB.x) + (vC.x + vD.x);
        a1 += (vA.y + vB.y) + (vC.y + vD.y);
    }
    for (; i < s1; i++) {
        int s = g_ssrc[i];
        float2 v = __half22float2(*(const __half2*)&g_hs16[s * HH + 2 * lane]);
        a0 += v.x; a1 += v.y;
    }
    float deg = (float)(s1 - s0);
    float2 hd = *(const float2*)&g_hd[n * HH + 2 * lane];
    int j0 = 2 * lane, j1 = 2 * lane + 1;
    float agg0 = a0 + deg * (hd.x + cb[j0]);
    float agg1 = a1 + deg * (hd.y + cb[j1]);
    float2 hold = *(const float2*)&g_h[n * HH + 2 * lane];
    float x0 = sigm(agg0) + softplus(hold.x);
    float x1 = sigm(agg1) + softplus(hold.y);
    x0 = gamma[j0] * (x0 - mean[j0]) * rsqrtf(var[j0] + EPS) + beta[j0];
    x1 = gamma[j1] * (x1 - mean[j1]) * rsqrtf(var[j1] + EPS) + beta[j1];
    x0 = fmaxf(x0, 0.0f);
    x1 = fmaxf(x1, 0.0f);
    if (!last) {
        *(float2*)&g_h[n * HH + 2 * lane] = make_float2(x0, x1);
    } else {
        float w0 = wrel[j0], w1 = wrel[j1];
        float hw0 = x0 * w0, hw1 = x1 * w1;
        float m = fmaxf(x0, x1);
        float mw = fmaxf(fabsf(hw0), fabsf(hw1));
        #pragma unroll
        for (int o = 16; o; o >>= 1) {
            m  = fmaxf(m,  __shfl_xor_sync(0xffffffffu, m,  o));
            mw = fmaxf(mw, __shfl_xor_sync(0xffffffffu, mw, o));
        }
        m = fmaxf(m, 1e-20f);
        mw = fmaxf(mw, 1e-20f);
        float invq = 65535.0f / m;
        float invw = 32767.0f / mw;
        unsigned q0 = __float2uint_rn(x0 * invq);
        unsigned q1 = __float2uint_rn(x1 * invq);
        unsigned b0 = (unsigned)(__float2int_rn(hw0 * invw) + 32768);
        unsigned b1 = (unsigned)(__float2int_rn(hw1 * invw) + 32768);
        *(unsigned*)&g_q[n * HH + 2 * lane]  = q0 | (q1 << 16);
        *(unsigned*)&g_qw[n * HH + 2 * lane] = b0 | (b1 << 16);
        if (lane == 0) {
            g_sB[n] = m * (1.0f / 65535.0f);
            g_sA[n] = mw * (1.0f / 32767.0f);
        }
    }
}

// ---------------- fused scoring: pos + K negs per edge, 8 threads/edge ----------
// hw_s[j] = (E(qw)-C2)*sA[s],  h_d[j] = (E(q)-C)*sB[d]
// score = ( sum_j (E(qw_j)-C2)*E(q_dj)  -  C*sum_j(E(qw_j)-C2) ) * sA[s]*sB[d]
__global__ void k_score(const int* __restrict__ src, const int* __restrict__ dst,
                        const int* __restrict__ neg_dst, float* __restrict__ out) {
    int gid = blockIdx.x * blockDim.x + threadIdx.x;
    int e = gid >> 3;
    int c = gid & 7;
    if (e >= EE) return;

    int s = src[e];
    int d = dst[e];
    int nd[KK];
    #pragma unroll
    for (int k = 0; k < KK; k++) nd[k] = neg_dst[e * KK + k];

    uint4 qs = *(const uint4*)&g_qw[s * HH + 8 * c];
    uint4 qp = *(const uint4*)&g_q[d * HH + 8 * c];
    uint4 qn[KK];
    #pragma unroll
    for (int k = 0; k < KK; k++)
        qn[k] = *(const uint4*)&g_q[nd[k] * HH + 8 * c];
    float sA = g_sA[s];
    float sBp = g_sB[d];
    float sBn[KK];
    #pragma unroll
    for (int k = 0; k < KK; k++) sBn[k] = g_sB[nd[k]];

    // src-side coefficients in count units
    float aw[8];
    const unsigned* vs = (const unsigned*)&qs;
    #pragma unroll
    for (int i = 0; i < 4; i++) {
        aw[2 * i]     = exlo(vs[i]) - MAGIC_C2;
        aw[2 * i + 1] = exhi(vs[i]) - MAGIC_C2;
    }
    float awsum = ((aw[0] + aw[1]) + (aw[2] + aw[3])) +
                  ((aw[4] + aw[5]) + (aw[6] + aw[7]));
    float base = -MAGIC_C * awsum;

    {
        const unsigned* vd = (const unsigned*)&qp;
        float p = base;
        #pragma unroll
        for (int i = 0; i < 4; i++) {
            p = fmaf(aw[2 * i],     exlo(vd[i]), p);
            p = fmaf(aw[2 * i + 1], exhi(vd[i]), p);
        }
        p += __shfl_xor_sync(0xffffffffu, p, 4);
        p += __shfl_xor_sync(0xffffffffu, p, 2);
        p += __shfl_xor_sync(0xffffffffu, p, 1);
        if (c == 0) out[e] = p * (sA * sBp);
    }
    #pragma unroll
    for (int k = 0; k < KK; k++) {
        const unsigned* vd = (const unsigned*)&qn[k];
        float p = base;
        #pragma unroll
        for (int i = 0; i < 4; i++) {
            p = fmaf(aw[2 * i],     exlo(vd[i]), p);
            p = fmaf(aw[2 * i + 1], exhi(vd[i]), p);
        }
        p += __shfl_xor_sync(0xffffffffu, p, 4);
        p += __shfl_xor_sync(0xffffffffu, p, 2);
        p += __shfl_xor_sync(0xffffffffu, p, 1);
        if (c == 0) out[EE + e * KK + k] = p * (sA * sBn[k]);
    }
}

// ---------------- launch ----------------
extern "C" void kernel_launch(void* const* d_in, const int* in_sizes, int n_in,
                              void* d_out, int out_size) {
    const float* node_feat = (const float*)d_in[0];
    const float* emb_w     = (const float*)d_in[1];
    const float* emb_b     = (const float*)d_in[2];
    const float* conv_w    = (const float*)d_in[3];
    const float* conv_b    = (const float*)d_in[4];
    const float* bn_gamma  = (const float*)d_in[5];
    const float* bn_beta   = (const float*)d_in[6];
    const float* bn_mean   = (const float*)d_in[7];
    const float* bn_var    = (const float*)d_in[8];
    const float* w_rel     = (const float*)d_in[9];
    const int*   src       = (const int*)d_in[10];
    const int*   dst       = (const int*)d_in[11];
    const int*   neg_dst   = (const int*)d_in[12];
    float* out = (float*)d_out;

    // side stream + fork/join events, created once (before any capture)
    static cudaStream_t s1 = nullptr;
    static cudaEvent_t eF = nullptr, eJ = nullptr;
    if (!s1) {
        cudaStreamCreateWithFlags(&s1, cudaStreamNonBlocking);
        cudaEventCreateWithFlags(&eF, cudaEventDisableTiming);
        cudaEventCreateWithFlags(&eJ, cudaEventDisableTiming);
    }

    // fork: CSR build on s1, concurrent with embed + lin0 on default stream
    cudaEventRecord(eF, 0);
    cudaStreamWaitEvent(s1, eF, 0);
    k_zero<<<(NN + 255) / 256, 256, 0, s1>>>();
    k_count<<<(EE + 255) / 256, 256, 0, s1>>>(dst);
    k_scan<<<1, 1024, 0, s1>>>();
    k_scatter<<<(EE + 255) / 256, 256, 0, s1>>>(src, dst);
    cudaEventRecord(eJ, s1);

    // embedding + first linear on default stream (independent of CSR)
    k_embed<<<(NN + 63) / 64, 256>>>(node_feat, emb_w, emb_b);
    k_lin<<<(NN + 63) / 64, 256>>>(conv_w);

    // join: gather needs CSR
    cudaStreamWaitEvent(0, eJ, 0);

    k_gather_update<<<(NN * 32 + 255) / 256, 256>>>(
        conv_b, bn_gamma, bn_beta, bn_mean, bn_var, w_rel, 0);

    k_lin<<<(NN + 63) / 64, 256>>>(conv_w + (size_t)2 * HH * HH);
    k_gather_update<<<(NN * 32 + 255) / 256, 256>>>(
        conv_b + HH, bn_gamma + HH, bn_beta + HH, bn_mean + HH, bn_var + HH,
        w_rel, 1);

    // fused scoring (uint16 dequant, per-node scales)
    k_score<<<(EE * 8 + 255) / 256, 256>>>(src, dst, neg_dst, out);
}

// round 11
// speedup vs baseline: 1.2416x; 1.1740x over previous
#include <cuda_runtime.h>
#include <cuda_fp16.h>
#include <math.h>

#define NN 50000
#define EE 800000
#define INF 128
#define HH 64
#define KK 5
#define EPS 0.001f

// ---------------- scratch (static device globals; no allocations) ----------------
__device__ __half g_h16[NN * HH];      // node hidden state (fp16 between stages)
__device__ __half g_hs16[NN * HH];     // hs = h@w_s, fp16 (gathered side)
__device__ float  g_hd[NN * HH];       // hd = h@w_d, fp32 (read once per node)
__device__ unsigned short g_q[NN * HH];  // final h, uint16, per-node scale sB
__device__ unsigned short g_qw[NN * HH]; // final h*w, biased uint16, per-node scale sA
__device__ float  g_sA[NN];            // src-side scale: rowmax|h*w| / 32767
__device__ float  g_sB[NN];            // dst-side scale: rowmax(h) / 65535
__device__ int    g_indeg[NN];
__device__ int    g_off[NN + 1];
__device__ int    g_cursor[NN];
__device__ int    g_ssrc[EE];          // src sorted by dst (CSR payload)
// packed weights: half2 of (W[2kk][n], W[2kk+1][n])  (k-pair, col)
__device__ unsigned g_Bemb[64 * 64];        // embed: kk=0..63 (K=128), n=0..63
__device__ unsigned g_Blin[2 * 32 * 128];   // lin l: kk=0..31 (K=64), j=0..127

// ---------------- helpers ----------------
__device__ __forceinline__ float sigm(float x) { return 1.0f / (1.0f + expf(-x)); }
__device__ __forceinline__ float softplus(float x) {
    return fmaxf(x, 0.0f) + log1pf(expf(-fabsf(x)));
}
#define MAGIC_C  8388608.0f   // 2^23
#define MAGIC_C2 8421376.0f   // 2^23 + 32768 (biased)

__device__ __forceinline__ float exlo(unsigned v) {
    return __uint_as_float(__byte_perm(v, 0x4B000000u, 0x7410));
}
__device__ __forceinline__ float exhi(unsigned v) {
    return __uint_as_float(__byte_perm(v, 0x4B000000u, 0x7432));
}
__device__ __forceinline__ unsigned packh2(float lo, float hi) {
    __half2 h = __floats2half2_rn(lo, hi);
    return *(unsigned*)&h;
}
__device__ __forceinline__ void mma16816(float& c0, float& c1, float& c2, float& c3,
                                         unsigned a0, unsigned a1, unsigned a2, unsigned a3,
                                         unsigned b0, unsigned b1) {
    asm volatile(
        "mma.sync.aligned.m16n8k16.row.col.f32.f16.f16.f32 "
        "{%0,%1,%2,%3},{%4,%5,%6,%7},{%8,%9},{%0,%1,%2,%3};"
        : "+f"(c0), "+f"(c1), "+f"(c2), "+f"(c3)
        : "r"(a0), "r"(a1), "r"(a2), "r"(a3), "r"(b0), "r"(b1));
}

// ---------------- weight prep: pack fp32 weights into k-pair half2 ----------------
__global__ void k_prep(const float* __restrict__ emb_w, const float* __restrict__ conv_w) {
    int i = blockIdx.x * blockDim.x + threadIdx.x;
    if (i < 64 * 64) {
        int kk = i >> 6, n = i & 63;
        g_Bemb[i] = packh2(emb_w[(2 * kk) * HH + n], emb_w[(2 * kk + 1) * HH + n]);
    } else if (i < 64 * 64 + 2 * 32 * 128) {
        int r = i - 64 * 64;
        int l = r >> 12;          // layer
        int q = r & 4095;
        int kk = q >> 7, j = q & 127;
        int k = 2 * kk;
        const float* W = conv_w + (size_t)l * 2 * HH * HH;
        float lo, hi;
        if (j < HH) { lo = W[k * HH + j];            hi = W[(k + 1) * HH + j]; }
        else        { lo = W[(HH + k) * HH + j - HH]; hi = W[(HH + k + 1) * HH + j - HH]; }
        g_Blin[r] = packh2(lo, hi);
    }
}

// ---------------- embed: h16 = fp16(node_feat) @ emb_w + emb_b  (tensor cores) ----
// block 256 = 8 warps; warp tile 16 rows x 64 cols; block 128 rows.
__global__ void k_embed(const float* __restrict__ x, const float* __restrict__ bias) {
    __shared__ unsigned sB[64 * 72];  // [kk][n], pitch 72 (conflict-free)
    int t = threadIdx.x;
    for (int i = t; i < 64 * 64; i += 256) {
        int kk = i >> 6, n = i & 63;
        sB[kk * 72 + n] = g_Bemb[i];
    }
    __syncthreads();
    int w = t >> 5, lane = t & 31;
    int g = lane >> 2, tig = lane & 3;
    int r0 = blockIdx.x * 128 + w * 16 + g;
    int r1 = r0 + 8;
    float C[8][4] = {};
    #pragma unroll
    for (int kb = 0; kb < INF; kb += 16) {
        unsigned a0 = 0, a1 = 0, a2 = 0, a3 = 0;
        if (r0 < NN) {
            float2 v = *(const float2*)&x[r0 * INF + kb + 2 * tig];
            float2 u = *(const float2*)&x[r0 * INF + kb + 8 + 2 * tig];
            a0 = packh2(v.x, v.y); a2 = packh2(u.x, u.y);
        }
        if (r1 < NN) {
            float2 v = *(const float2*)&x[r1 * INF + kb + 2 * tig];
            float2 u = *(const float2*)&x[r1 * INF + kb + 8 + 2 * tig];
            a1 = packh2(v.x, v.y); a3 = packh2(u.x, u.y);
        }
        int kk = kb >> 1;
        #pragma unroll
        for (int n = 0; n < 8; n++) {
            unsigned b0 = sB[(kk + tig) * 72 + n * 8 + g];
            unsigned b1 = sB[(kk + 4 + tig) * 72 + n * 8 + g];
            mma16816(C[n][0], C[n][1], C[n][2], C[n][3], a0, a1, a2, a3, b0, b1);
        }
    }
    #pragma unroll
    for (int n = 0; n < 8; n++) {
        int j = n * 8 + 2 * tig;
        float bx = bias[j], by = bias[j + 1];
        if (r0 < NN)
            *(__half2*)&g_h16[r0 * HH + j] = __floats2half2_rn(C[n][0] + bx, C[n][1] + by);
        if (r1 < NN)
            *(__half2*)&g_h16[r1 * HH + j] = __floats2half2_rn(C[n][2] + bx, C[n][3] + by);
    }
}

// ---------------- lin: [hs16 | hd] = h16 @ [Ws | Wd]  (tensor cores) --------------
// block 256 = 8 warps; warp tile 16 rows x 128 cols; block 128 rows.
__global__ void k_lin(int layer) {
    __shared__ unsigned sB[32 * 136];  // [kk][j], pitch 136 (conflict-free)
    int t = threadIdx.x;
    const unsigned* Bl = g_Blin + layer * 32 * 128;
    for (int i = t; i < 32 * 128; i += 256) {
        int kk = i >> 7, j = i & 127;
        sB[kk * 136 + j] = Bl[i];
    }
    __syncthreads();
    int w = t >> 5, lane = t & 31;
    int g = lane >> 2, tig = lane & 3;
    int r0 = blockIdx.x * 128 + w * 16 + g;
    int r1 = r0 + 8;
    float C[16][4] = {};
    #pragma unroll
    for (int kb = 0; kb < HH; kb += 16) {
        unsigned a0 = 0, a1 = 0, a2 = 0, a3 = 0;
        if (r0 < NN) {
            a0 = *(const unsigned*)&g_h16[r0 * HH + kb + 2 * tig];
            a2 = *(const unsigned*)&g_h16[r0 * HH + kb + 8 + 2 * tig];
        }
        if (r1 < NN) {
            a1 = *(const unsigned*)&g_h16[r1 * HH + kb + 2 * tig];
            a3 = *(const unsigned*)&g_h16[r1 * HH + kb + 8 + 2 * tig];
        }
        int kk = kb >> 1;
        #pragma unroll
        for (int n = 0; n < 16; n++) {
            unsigned b0 = sB[(kk + tig) * 136 + n * 8 + g];
            unsigned b1 = sB[(kk + 4 + tig) * 136 + n * 8 + g];
            mma16816(C[n][0], C[n][1], C[n][2], C[n][3], a0, a1, a2, a3, b0, b1);
        }
    }
    #pragma unroll
    for (int n = 0; n < 16; n++) {
        int j = n * 8 + 2 * tig;
        if (j < HH) {  // hs -> fp16
            if (r0 < NN)
                *(__half2*)&g_hs16[r0 * HH + j] = __floats2half2_rn(C[n][0], C[n][1]);
            if (r1 < NN)
                *(__half2*)&g_hs16[r1 * HH + j] = __floats2half2_rn(C[n][2], C[n][3]);
        } else {       // hd -> fp32
            int jd = j - HH;
            if (r0 < NN) *(float2*)&g_hd[r0 * HH + jd] = make_float2(C[n][0], C[n][1]);
            if (r1 < NN) *(float2*)&g_hd[r1 * HH + jd] = make_float2(C[n][2], C[n][3]);
        }
    }
}

// ---------------- CSR build ----------------
__global__ void k_zero() {
    int i = blockIdx.x * blockDim.x + threadIdx.x;
    if (i < NN) { g_indeg[i] = 0; g_cursor[i] = 0; }
}
__global__ void k_count(const int* __restrict__ dst) {
    int e = blockIdx.x * blockDim.x + threadIdx.x;
    if (e < EE) atomicAdd(&g_indeg[dst[e]], 1);
}
__global__ void k_scan() {  // single block, 1024 threads
    __shared__ int ssum[1024];
    int t = threadIdx.x;
    const int CH = (NN + 1023) / 1024;
    int base = t * CH;
    int s = 0;
    for (int i = 0; i < CH; i++) {
        int idx = base + i;
        if (idx < NN) s += g_indeg[idx];
    }
    ssum[t] = s;
    __syncthreads();
    for (int off = 1; off < 1024; off <<= 1) {
        int v = (t >= off) ? ssum[t - off] : 0;
        __syncthreads();
        ssum[t] += v;
        __syncthreads();
    }
    int run = ssum[t] - s;  // exclusive prefix
    for (int i = 0; i < CH; i++) {
        int idx = base + i;
        if (idx < NN) { g_off[idx] = run; run += g_indeg[idx]; }
    }
    if (t == 1023) g_off[NN] = run;
}
__global__ void k_scatter(const int* __restrict__ src, const int* __restrict__ dst) {
    int e = blockIdx.x * blockDim.x + threadIdx.x;
    if (e < EE) {
        int d = dst[e];
        int p = atomicAdd(&g_cursor[d], 1);
        g_ssrc[g_off[d] + p] = src[e];
    }
}

// ---------------- gather + full node update (one warp per node) ----------------
// last==0: writes fp16 g_h16.
// last==1: quantizes in-register (per-node scales) -> g_q, g_qw, g_sA, g_sB.
__global__ void k_gather_update(const float* __restrict__ cb,
                                const float* __restrict__ gamma,
                                const float* __restrict__ beta,
                                const float* __restrict__ mean,
                                const float* __restrict__ var,
                                const float* __restrict__ wrel,
                                int last) {
    int warp = (blockIdx.x * blockDim.x + threadIdx.x) >> 5;
    int lane = threadIdx.x & 31;
    if (warp >= NN) return;
    int n = warp;
    int s0 = g_off[n], s1 = g_off[n + 1];
    float a0 = 0.0f, a1 = 0.0f;
    int i = s0;
    for (; i + 3 < s1; i += 4) {
        int sA = g_ssrc[i], sB = g_ssrc[i + 1], sC = g_ssrc[i + 2], sD = g_ssrc[i + 3];
        float2 vA = __half22float2(*(const __half2*)&g_hs16[sA * HH + 2 * lane]);
        float2 vB = __half22float2(*(const __half2*)&g_hs16[sB * HH + 2 * lane]);
        float2 vC = __half22float2(*(const __half2*)&g_hs16[sC * HH + 2 * lane]);
        float2 vD = __half22float2(*(const __half2*)&g_hs16[sD * HH + 2 * lane]);
        a0 += (vA.x + vB.x) + (vC.x + vD.x);
        a1 += (vA.y + vB.y) + (vC.y + vD.y);
    }
    for (; i < s1; i++) {
        int s = g_ssrc[i];
        float2 v = __half22float2(*(const __half2*)&g_hs16[s * HH + 2 * lane]);
        a0 += v.x; a1 += v.y;
    }
    float deg = (float)(s1 - s0);
    float2 hd = *(const float2*)&g_hd[n * HH + 2 * lane];
    int j0 = 2 * lane, j1 = 2 * lane + 1;
    float agg0 = a0 + deg * (hd.x + cb[j0]);
    float agg1 = a1 + deg * (hd.y + cb[j1]);
    float2 hold = __half22float2(*(const __half2*)&g_h16[n * HH + 2 * lane]);
    float x0 = sigm(agg0) + softplus(hold.x);
    float x1 = sigm(agg1) + softplus(hold.y);
    x0 = gamma[j0] * (x0 - mean[j0]) * rsqrtf(var[j0] + EPS) + beta[j0];
    x1 = gamma[j1] * (x1 - mean[j1]) * rsqrtf(var[j1] + EPS) + beta[j1];
    x0 = fmaxf(x0, 0.0f);
    x1 = fmaxf(x1, 0.0f);
    if (!last) {
        *(__half2*)&g_h16[n * HH + 2 * lane] = __floats2half2_rn(x0, x1);
    } else {
        float w0 = wrel[j0], w1 = wrel[j1];
        float hw0 = x0 * w0, hw1 = x1 * w1;
        float m = fmaxf(x0, x1);
        float mw = fmaxf(fabsf(hw0), fabsf(hw1));
        #pragma unroll
        for (int o = 16; o; o >>= 1) {
            m  = fmaxf(m,  __shfl_xor_sync(0xffffffffu, m,  o));
            mw = fmaxf(mw, __shfl_xor_sync(0xffffffffu, mw, o));
        }
        m = fmaxf(m, 1e-20f);
        mw = fmaxf(mw, 1e-20f);
        float invq = 65535.0f / m;
        float invw = 32767.0f / mw;
        unsigned q0 = __float2uint_rn(x0 * invq);
        unsigned q1 = __float2uint_rn(x1 * invq);
        unsigned b0 = (unsigned)(__float2int_rn(hw0 * invw) + 32768);
        unsigned b1 = (unsigned)(__float2int_rn(hw1 * invw) + 32768);
        *(unsigned*)&g_q[n * HH + 2 * lane]  = q0 | (q1 << 16);
        *(unsigned*)&g_qw[n * HH + 2 * lane] = b0 | (b1 << 16);
        if (lane == 0) {
            g_sB[n] = m * (1.0f / 65535.0f);
            g_sA[n] = mw * (1.0f / 32767.0f);
        }
    }
}

// ---------------- fused scoring: pos + K negs per edge, 8 threads/edge ----------
__global__ void k_score(const int* __restrict__ src, const int* __restrict__ dst,
                        const int* __restrict__ neg_dst, float* __restrict__ out) {
    int gid = blockIdx.x * blockDim.x + threadIdx.x;
    int e = gid >> 3;
    int c = gid & 7;
    if (e >= EE) return;

    int s = src[e];
    int d = dst[e];
    int nd[KK];
    #pragma unroll
    for (int k = 0; k < KK; k++) nd[k] = neg_dst[e * KK + k];

    uint4 qs = *(const uint4*)&g_qw[s * HH + 8 * c];
    uint4 qp = *(const uint4*)&g_q[d * HH + 8 * c];
    uint4 qn[KK];
    #pragma unroll
    for (int k = 0; k < KK; k++)
        qn[k] = *(const uint4*)&g_q[nd[k] * HH + 8 * c];
    float sA = g_sA[s];
    float sBp = g_sB[d];
    float sBn[KK];
    #pragma unroll
    for (int k = 0; k < KK; k++) sBn[k] = g_sB[nd[k]];

    float aw[8];
    const unsigned* vs = (const unsigned*)&qs;
    #pragma unroll
    for (int i = 0; i < 4; i++) {
        aw[2 * i]     = exlo(vs[i]) - MAGIC_C2;
        aw[2 * i + 1] = exhi(vs[i]) - MAGIC_C2;
    }
    float awsum = ((aw[0] + aw[1]) + (aw[2] + aw[3])) +
                  ((aw[4] + aw[5]) + (aw[6] + aw[7]));
    float base = -MAGIC_C * awsum;

    {
        const unsigned* vd = (const unsigned*)&qp;
        float p = base;
        #pragma unroll
        for (int i = 0; i < 4; i++) {
            p = fmaf(aw[2 * i],     exlo(vd[i]), p);
            p = fmaf(aw[2 * i + 1], exhi(vd[i]), p);
        }
        p += __shfl_xor_sync(0xffffffffu, p, 4);
        p += __shfl_xor_sync(0xffffffffu, p, 2);
        p += __shfl_xor_sync(0xffffffffu, p, 1);
        if (c == 0) out[e] = p * (sA * sBp);
    }
    #pragma unroll
    for (int k = 0; k < KK; k++) {
        const unsigned* vd = (const unsigned*)&qn[k];
        float p = base;
        #pragma unroll
        for (int i = 0; i < 4; i++) {
            p = fmaf(aw[2 * i],     exlo(vd[i]), p);
            p = fmaf(aw[2 * i + 1], exhi(vd[i]), p);
        }
        p += __shfl_xor_sync(0xffffffffu, p, 4);
        p += __shfl_xor_sync(0xffffffffu, p, 2);
        p += __shfl_xor_sync(0xffffffffu, p, 1);
        if (c == 0) out[EE + e * KK + k] = p * (sA * sBn[k]);
    }
}

// ---------------- launch ----------------
extern "C" void kernel_launch(void* const* d_in, const int* in_sizes, int n_in,
                              void* d_out, int out_size) {
    const float* node_feat = (const float*)d_in[0];
    const float* emb_w     = (const float*)d_in[1];
    const float* emb_b     = (const float*)d_in[2];
    const float* conv_w    = (const float*)d_in[3];
    const float* conv_b    = (const float*)d_in[4];
    const float* bn_gamma  = (const float*)d_in[5];
    const float* bn_beta   = (const float*)d_in[6];
    const float* bn_mean   = (const float*)d_in[7];
    const float* bn_var    = (const float*)d_in[8];
    const float* w_rel     = (const float*)d_in[9];
    const int*   src       = (const int*)d_in[10];
    const int*   dst       = (const int*)d_in[11];
    const int*   neg_dst   = (const int*)d_in[12];
    float* out = (float*)d_out;

    // side stream + fork/join events, created once (before any capture)
    static cudaStream_t s1 = nullptr;
    static cudaEvent_t eF = nullptr, eJ = nullptr;
    if (!s1) {
        cudaStreamCreateWithFlags(&s1, cudaStreamNonBlocking);
        cudaEventCreateWithFlags(&eF, cudaEventDisableTiming);
        cudaEventCreateWithFlags(&eJ, cudaEventDisableTiming);
    }

    // fork: CSR build on s1, concurrent with prep+embed+lin0 on default stream
    cudaEventRecord(eF, 0);
    cudaStreamWaitEvent(s1, eF, 0);
    k_zero<<<(NN + 255) / 256, 256, 0, s1>>>();
    k_count<<<(EE + 255) / 256, 256, 0, s1>>>(dst);
    k_scan<<<1, 1024, 0, s1>>>();
    k_scatter<<<(EE + 255) / 256, 256, 0, s1>>>(src, dst);
    cudaEventRecord(eJ, s1);

    // weight prep + embedding + first linear (tensor cores)
    k_prep<<<48, 256>>>(emb_w, conv_w);
    k_embed<<<(NN + 127) / 128, 256>>>(node_feat, emb_b);
    k_lin<<<(NN + 127) / 128, 256>>>(0);

    // join: gather needs CSR
    cudaStreamWaitEvent(0, eJ, 0);

    k_gather_update<<<(NN * 32 + 255) / 256, 256>>>(
        conv_b, bn_gamma, bn_beta, bn_mean, bn_var, w_rel, 0);

    k_lin<<<(NN + 127) / 128, 256>>>(1);
    k_gather_update<<<(NN * 32 + 255) / 256, 256>>>(
        conv_b + HH, bn_gamma + HH, bn_beta + HH, bn_mean + HH, bn_var + HH,
        w_rel, 1);

    // fused scoring (uint16 dequant, per-node scales)
    k_score<<<(EE * 8 + 255) / 256, 256>>>(src, dst, neg_dst, out);
}